// round 2
// baseline (speedup 1.0000x reference)
#include <cuda_runtime.h>
#include <cuda_bf16.h>

// Problem constants
#define BATCH 4
#define CH    256
#define G     8
#define HD    32
#define L     3136      // 56*56
#define BG    32        // BATCH*G
#define TJ    64
#define TK    64
#define NT    49        // L/64
#define LOG2E 1.4426950408889634f

// Scratch (static device arrays; no allocations allowed)
__device__ float g_q[BG * HD * L];   // (bg, d, l), q pre-scaled by log2(e)
__device__ float g_k[BG * HD * L];   // (bg, d, l)
__device__ float g_v[BG * HD * L];   // (bg, d, l)
__device__ float g_m[BG * L];        // row max (log2 domain)
__device__ float g_rz[BG * L];       // 1 / row sum

// ---------------------------------------------------------------------------
// Kernel 1: grouped 1x1 conv -> q, k, v.  q scaled by log2(e).
// grid (49, 32), block 256
// ---------------------------------------------------------------------------
__global__ void qkv_kernel(const float* __restrict__ x,
                           const float* __restrict__ Wq, const float* __restrict__ bq,
                           const float* __restrict__ Wk, const float* __restrict__ bk,
                           const float* __restrict__ Wv, const float* __restrict__ bv)
{
    int bg = blockIdx.y;
    int l0 = blockIdx.x * 64;
    int b = bg >> 3, g = bg & 7;

    __shared__ float wqs[HD * HD], wks[HD * HD], wvs[HD * HD];
    __shared__ float bqs[HD], bks[HD], bvs[HD];
    __shared__ float xs[HD][64];

    int tid = threadIdx.x;
    for (int i = tid; i < HD * HD; i += 256) {
        wqs[i] = Wq[g * HD * HD + i] * LOG2E;
        wks[i] = Wk[g * HD * HD + i];
        wvs[i] = Wv[g * HD * HD + i];
    }
    if (tid < HD) {
        bqs[tid] = bq[g * HD + tid] * LOG2E;
        bks[tid] = bk[g * HD + tid];
        bvs[tid] = bv[g * HD + tid];
    }
    const float* xp = x + ((size_t)b * CH + g * HD) * L + l0;
    for (int i = tid; i < HD * 64; i += 256) {
        int d = i >> 6, l = i & 63;
        xs[d][l] = xp[(size_t)d * L + l];
    }
    __syncthreads();

    int l  = tid & 63;
    int o0 = (tid >> 6) * 8;
    float qa[8], ka[8], va[8];
#pragma unroll
    for (int r = 0; r < 8; r++) { qa[r] = bqs[o0 + r]; ka[r] = bks[o0 + r]; va[r] = bvs[o0 + r]; }
#pragma unroll
    for (int i = 0; i < HD; i++) {
        float xv = xs[i][l];
#pragma unroll
        for (int r = 0; r < 8; r++) {
            qa[r] += wqs[(o0 + r) * HD + i] * xv;
            ka[r] += wks[(o0 + r) * HD + i] * xv;
            va[r] += wvs[(o0 + r) * HD + i] * xv;
        }
    }
    size_t base = (size_t)bg * HD * L + l0 + l;
#pragma unroll
    for (int r = 0; r < 8; r++) {
        g_q[base + (size_t)(o0 + r) * L] = qa[r];
        g_k[base + (size_t)(o0 + r) * L] = ka[r];
        g_v[base + (size_t)(o0 + r) * L] = va[r];
    }
}

// ---------------------------------------------------------------------------
// Kernel 2: per-row online softmax stats over e[j,k] = q_j . k_k (log2 domain)
// grid (49, 32), block 256.  Thread (jg, kg) owns 4 rows x 4 cols per tile.
// ---------------------------------------------------------------------------
__global__ void pass1_kernel()
{
    int bg = blockIdx.y;
    int j0 = blockIdx.x * TJ;

    __shared__ float qs[HD][TJ];
    __shared__ float ks[HD][TK];

    int tid = threadIdx.x;
    const float* qp = g_q + (size_t)bg * HD * L;
    const float* kp = g_k + (size_t)bg * HD * L;

    for (int i = tid; i < HD * TJ; i += 256) {
        int d = i >> 6, jj = i & 63;
        qs[d][jj] = qp[(size_t)d * L + j0 + jj];
    }

    int jg = tid >> 4;   // 0..15 (row group); 16 lanes per row set = half warp
    int kg = tid & 15;   // 0..15 (col group)

    float m[4], s[4];
#pragma unroll
    for (int r = 0; r < 4; r++) { m[r] = -1e30f; s[r] = 0.f; }

    for (int kt = 0; kt < NT; kt++) {
        __syncthreads();
        for (int i = tid; i < HD * TK; i += 256) {
            int d = i >> 6, kk = i & 63;
            ks[d][kk] = kp[(size_t)d * L + kt * TK + kk];
        }
        __syncthreads();

        float e[4][4];
#pragma unroll
        for (int a = 0; a < 4; a++)
#pragma unroll
            for (int c = 0; c < 4; c++) e[a][c] = 0.f;

#pragma unroll
        for (int d = 0; d < HD; d++) {
            float4 qv = *(const float4*)&qs[d][jg * 4];
            float4 kv = *(const float4*)&ks[d][kg * 4];
            float qq[4] = {qv.x, qv.y, qv.z, qv.w};
            float kk2[4] = {kv.x, kv.y, kv.z, kv.w};
#pragma unroll
            for (int a = 0; a < 4; a++)
#pragma unroll
                for (int c = 0; c < 4; c++) e[a][c] += qq[a] * kk2[c];
        }

#pragma unroll
        for (int a = 0; a < 4; a++) {
            float mx = fmaxf(fmaxf(e[a][0], e[a][1]), fmaxf(e[a][2], e[a][3]));
            float mn = fmaxf(m[a], mx);
            float ss = exp2f(e[a][0] - mn) + exp2f(e[a][1] - mn)
                     + exp2f(e[a][2] - mn) + exp2f(e[a][3] - mn);
            s[a] = s[a] * exp2f(m[a] - mn) + ss;
            m[a] = mn;
        }
    }

    // reduce (m, s) across the 16 lanes sharing each row
#pragma unroll
    for (int mask = 8; mask; mask >>= 1) {
#pragma unroll
        for (int a = 0; a < 4; a++) {
            float om = __shfl_xor_sync(0xffffffff, m[a], mask);
            float os = __shfl_xor_sync(0xffffffff, s[a], mask);
            float mn = fmaxf(m[a], om);
            s[a] = s[a] * exp2f(m[a] - mn) + os * exp2f(om - mn);
            m[a] = mn;
        }
    }
    if (kg == 0) {
#pragma unroll
        for (int a = 0; a < 4; a++) {
            int j = j0 + jg * 4 + a;
            g_m[bg * L + j]  = m[a];
            g_rz[bg * L + j] = 1.0f / s[a];
        }
    }
}

// ---------------------------------------------------------------------------
// Kernel 3: out[d,k] = sum_j exp2(e[j,k]-m_j) * v[d,j]/Z_j   (+ x residual)
// grid (49, 32), block 256.  Block owns 64 output columns x all 32 d.
// ---------------------------------------------------------------------------
__global__ void pass2_kernel(const float* __restrict__ x, float* __restrict__ out)
{
    int bg = blockIdx.y;
    int k0 = blockIdx.x * TK;

    __shared__ float ks2[HD][TK];          // K for our columns (the "queries")
    __shared__ float qs[HD][TJ];           // Q tile (the "keys")
    __shared__ float wst[TJ][HD + 4];      // w = v/Z, transposed [jj][d]
    __shared__ float ps[TJ][TK + 4];       // P tile
    __shared__ float ms[TJ];

    int tid = threadIdx.x;
    const float* qp = g_q + (size_t)bg * HD * L;
    const float* kp = g_k + (size_t)bg * HD * L;
    const float* vp = g_v + (size_t)bg * HD * L;

    for (int i = tid; i < HD * TK; i += 256) {
        int d = i >> 6, kk = i & 63;
        ks2[d][kk] = kp[(size_t)d * L + k0 + kk];
    }

    int jg = tid >> 4, kg = tid & 15;   // P-compute mapping
    int kq = tid & 63;                  // out col
    int dg = tid >> 6;                  // 0..3 -> d base = dg*8

    float acc[8];
#pragma unroll
    for (int r = 0; r < 8; r++) acc[r] = 0.f;

    for (int jt = 0; jt < NT; jt++) {
        __syncthreads();
        int j0 = jt * TJ;
        for (int i = tid; i < HD * TJ; i += 256) {
            int d = i >> 6, jj = i & 63;
            qs[d][jj] = qp[(size_t)d * L + j0 + jj];
            float rz = g_rz[bg * L + j0 + jj];
            wst[jj][d] = vp[(size_t)d * L + j0 + jj] * rz;
        }
        if (tid < TJ) ms[tid] = g_m[bg * L + j0 + tid];
        __syncthreads();

        // P = exp2(Q^T Ks - m)
        float e[4][4];
#pragma unroll
        for (int a = 0; a < 4; a++)
#pragma unroll
            for (int c = 0; c < 4; c++) e[a][c] = 0.f;
#pragma unroll
        for (int d = 0; d < HD; d++) {
            float4 qv = *(const float4*)&qs[d][jg * 4];
            float4 kv = *(const float4*)&ks2[d][kg * 4];
            float qq[4] = {qv.x, qv.y, qv.z, qv.w};
            float kk2[4] = {kv.x, kv.y, kv.z, kv.w};
#pragma unroll
            for (int a = 0; a < 4; a++)
#pragma unroll
                for (int c = 0; c < 4; c++) e[a][c] += qq[a] * kk2[c];
        }
#pragma unroll
        for (int a = 0; a < 4; a++) {
            float mj = ms[jg * 4 + a];
            float4 pv;
            pv.x = exp2f(e[a][0] - mj);
            pv.y = exp2f(e[a][1] - mj);
            pv.z = exp2f(e[a][2] - mj);
            pv.w = exp2f(e[a][3] - mj);
            *(float4*)&ps[jg * 4 + a][kg * 4] = pv;
        }
        __syncthreads();

        // out[dg*8 + r][kq] += sum_jj P[jj][kq] * w[jj][dg*8 + r]
#pragma unroll 4
        for (int jj = 0; jj < TJ; jj++) {
            float p = ps[jj][kq];
            float4 w0 = *(const float4*)&wst[jj][dg * 8];
            float4 w1 = *(const float4*)&wst[jj][dg * 8 + 4];
            acc[0] += p * w0.x; acc[1] += p * w0.y;
            acc[2] += p * w0.z; acc[3] += p * w0.w;
            acc[4] += p * w1.x; acc[5] += p * w1.y;
            acc[6] += p * w1.z; acc[7] += p * w1.w;
        }
    }

    // epilogue: residual add, write NCHW
    int b = bg >> 3, g = bg & 7;
    size_t cbase = ((size_t)b * CH + g * HD + dg * 8) * L + k0 + kq;
#pragma unroll
    for (int r = 0; r < 8; r++) {
        out[cbase + (size_t)r * L] = acc[r] + x[cbase + (size_t)r * L];
    }
}

// ---------------------------------------------------------------------------
extern "C" void kernel_launch(void* const* d_in, const int* in_sizes, int n_in,
                              void* d_out, int out_size)
{
    (void)in_sizes; (void)n_in; (void)out_size;
    const float* x  = (const float*)d_in[0];
    const float* Wq = (const float*)d_in[1];
    const float* bq = (const float*)d_in[2];
    const float* Wk = (const float*)d_in[3];
    const float* bk = (const float*)d_in[4];
    const float* Wv = (const float*)d_in[5];
    const float* bv = (const float*)d_in[6];
    float* out = (float*)d_out;

    dim3 grid(NT, BG);
    qkv_kernel<<<grid, 256>>>(x, Wq, bq, Wk, bk, Wv, bv);
    pass1_kernel<<<grid, 256>>>();
    pass2_kernel<<<grid, 256>>>(x, out);
}

// round 3
// speedup vs baseline: 1.0018x; 1.0018x over previous
#include <cuda_runtime.h>
#include <cuda_bf16.h>

// Problem constants
#define BATCH 4
#define CH    256
#define G     8
#define HD    32
#define L     3136      // 56*56
#define BG    32        // BATCH*G
#define TJ    64
#define TK    64
#define NT    49        // L/64
#define LOG2E 1.4426950408889634f

// Scratch (static device arrays; no allocations allowed)
__device__ float g_q[BG * HD * L];   // (bg, d, l), q pre-scaled by log2(e)
__device__ float g_k[BG * HD * L];   // (bg, d, l)
__device__ float g_v[BG * HD * L];   // (bg, d, l)
__device__ float g_m[BG * L];        // row max (log2 domain)
__device__ float g_rz[BG * L];       // 1 / row sum

// ---------------------------------------------------------------------------
// Kernel 1: grouped 1x1 conv -> q, k, v.  q scaled by log2(e).
// grid (49, 32), block 256
// ---------------------------------------------------------------------------
__global__ void qkv_kernel(const float* __restrict__ x,
                           const float* __restrict__ Wq, const float* __restrict__ bq,
                           const float* __restrict__ Wk, const float* __restrict__ bk,
                           const float* __restrict__ Wv, const float* __restrict__ bv)
{
    int bg = blockIdx.y;
    int l0 = blockIdx.x * 64;
    int b = bg >> 3, g = bg & 7;

    __shared__ float wqs[HD * HD], wks[HD * HD], wvs[HD * HD];
    __shared__ float bqs[HD], bks[HD], bvs[HD];
    __shared__ float xs[HD][64];

    int tid = threadIdx.x;
    for (int i = tid; i < HD * HD; i += 256) {
        wqs[i] = Wq[g * HD * HD + i] * LOG2E;
        wks[i] = Wk[g * HD * HD + i];
        wvs[i] = Wv[g * HD * HD + i];
    }
    if (tid < HD) {
        bqs[tid] = bq[g * HD + tid] * LOG2E;
        bks[tid] = bk[g * HD + tid];
        bvs[tid] = bv[g * HD + tid];
    }
    const float* xp = x + ((size_t)b * CH + g * HD) * L + l0;
    for (int i = tid; i < HD * 64; i += 256) {
        int d = i >> 6, l = i & 63;
        xs[d][l] = xp[(size_t)d * L + l];
    }
    __syncthreads();

    int l  = tid & 63;
    int o0 = (tid >> 6) * 8;
    float qa[8], ka[8], va[8];
#pragma unroll
    for (int r = 0; r < 8; r++) { qa[r] = bqs[o0 + r]; ka[r] = bks[o0 + r]; va[r] = bvs[o0 + r]; }
#pragma unroll
    for (int i = 0; i < HD; i++) {
        float xv = xs[i][l];
#pragma unroll
        for (int r = 0; r < 8; r++) {
            qa[r] += wqs[(o0 + r) * HD + i] * xv;
            ka[r] += wks[(o0 + r) * HD + i] * xv;
            va[r] += wvs[(o0 + r) * HD + i] * xv;
        }
    }
    size_t base = (size_t)bg * HD * L + l0 + l;
#pragma unroll
    for (int r = 0; r < 8; r++) {
        g_q[base + (size_t)(o0 + r) * L] = qa[r];
        g_k[base + (size_t)(o0 + r) * L] = ka[r];
        g_v[base + (size_t)(o0 + r) * L] = va[r];
    }
}

// ---------------------------------------------------------------------------
// Kernel 2: per-row online softmax stats over e[j,k] = q_j . k_k (log2 domain)
// grid (49, 32), block 256.  Thread (jg, kg) owns 4 rows x 4 cols per tile.
// ---------------------------------------------------------------------------
__global__ void pass1_kernel()
{
    int bg = blockIdx.y;
    int j0 = blockIdx.x * TJ;

    __shared__ float qs[HD][TJ];
    __shared__ float ks[HD][TK];

    int tid = threadIdx.x;
    const float* qp = g_q + (size_t)bg * HD * L;
    const float* kp = g_k + (size_t)bg * HD * L;

    for (int i = tid; i < HD * TJ; i += 256) {
        int d = i >> 6, jj = i & 63;
        qs[d][jj] = qp[(size_t)d * L + j0 + jj];
    }

    int jg = tid >> 4;   // 0..15 (row group); 16 lanes per row set = half warp
    int kg = tid & 15;   // 0..15 (col group)

    float m[4], s[4];
#pragma unroll
    for (int r = 0; r < 4; r++) { m[r] = -1e30f; s[r] = 0.f; }

    for (int kt = 0; kt < NT; kt++) {
        __syncthreads();
        for (int i = tid; i < HD * TK; i += 256) {
            int d = i >> 6, kk = i & 63;
            ks[d][kk] = kp[(size_t)d * L + kt * TK + kk];
        }
        __syncthreads();

        float e[4][4];
#pragma unroll
        for (int a = 0; a < 4; a++)
#pragma unroll
            for (int c = 0; c < 4; c++) e[a][c] = 0.f;

#pragma unroll
        for (int d = 0; d < HD; d++) {
            float4 qv = *(const float4*)&qs[d][jg * 4];
            float4 kv = *(const float4*)&ks[d][kg * 4];
            float qq[4] = {qv.x, qv.y, qv.z, qv.w};
            float kk2[4] = {kv.x, kv.y, kv.z, kv.w};
#pragma unroll
            for (int a = 0; a < 4; a++)
#pragma unroll
                for (int c = 0; c < 4; c++) e[a][c] += qq[a] * kk2[c];
        }

#pragma unroll
        for (int a = 0; a < 4; a++) {
            float mx = fmaxf(fmaxf(e[a][0], e[a][1]), fmaxf(e[a][2], e[a][3]));
            float mn = fmaxf(m[a], mx);
            float ss = exp2f(e[a][0] - mn) + exp2f(e[a][1] - mn)
                     + exp2f(e[a][2] - mn) + exp2f(e[a][3] - mn);
            s[a] = s[a] * exp2f(m[a] - mn) + ss;
            m[a] = mn;
        }
    }

    // reduce (m, s) across the 16 lanes sharing each row
#pragma unroll
    for (int mask = 8; mask; mask >>= 1) {
#pragma unroll
        for (int a = 0; a < 4; a++) {
            float om = __shfl_xor_sync(0xffffffff, m[a], mask);
            float os = __shfl_xor_sync(0xffffffff, s[a], mask);
            float mn = fmaxf(m[a], om);
            s[a] = s[a] * exp2f(m[a] - mn) + os * exp2f(om - mn);
            m[a] = mn;
        }
    }
    if (kg == 0) {
#pragma unroll
        for (int a = 0; a < 4; a++) {
            int j = j0 + jg * 4 + a;
            g_m[bg * L + j]  = m[a];
            g_rz[bg * L + j] = 1.0f / s[a];
        }
    }
}

// ---------------------------------------------------------------------------
// Kernel 3: out[d,k] = sum_j exp2(e[j,k]-m_j) * v[d,j]/Z_j   (+ x residual)
// grid (49, 32), block 256.  Block owns 64 output columns x all 32 d.
// ---------------------------------------------------------------------------
__global__ void pass2_kernel(const float* __restrict__ x, float* __restrict__ out)
{
    int bg = blockIdx.y;
    int k0 = blockIdx.x * TK;

    __shared__ float ks2[HD][TK];          // K for our columns (the "queries")
    __shared__ float qs[HD][TJ];           // Q tile (the "keys")
    __shared__ float wst[TJ][HD + 4];      // w = v/Z, transposed [jj][d]
    __shared__ float ps[TJ][TK + 4];       // P tile
    __shared__ float ms[TJ];

    int tid = threadIdx.x;
    const float* qp = g_q + (size_t)bg * HD * L;
    const float* kp = g_k + (size_t)bg * HD * L;
    const float* vp = g_v + (size_t)bg * HD * L;

    for (int i = tid; i < HD * TK; i += 256) {
        int d = i >> 6, kk = i & 63;
        ks2[d][kk] = kp[(size_t)d * L + k0 + kk];
    }

    int jg = tid >> 4, kg = tid & 15;   // P-compute mapping
    int kq = tid & 63;                  // out col
    int dg = tid >> 6;                  // 0..3 -> d base = dg*8

    float acc[8];
#pragma unroll
    for (int r = 0; r < 8; r++) acc[r] = 0.f;

    for (int jt = 0; jt < NT; jt++) {
        __syncthreads();
        int j0 = jt * TJ;
        for (int i = tid; i < HD * TJ; i += 256) {
            int d = i >> 6, jj = i & 63;
            qs[d][jj] = qp[(size_t)d * L + j0 + jj];
            float rz = g_rz[bg * L + j0 + jj];
            wst[jj][d] = vp[(size_t)d * L + j0 + jj] * rz;
        }
        if (tid < TJ) ms[tid] = g_m[bg * L + j0 + tid];
        __syncthreads();

        // P = exp2(Q^T Ks - m)
        float e[4][4];
#pragma unroll
        for (int a = 0; a < 4; a++)
#pragma unroll
            for (int c = 0; c < 4; c++) e[a][c] = 0.f;
#pragma unroll
        for (int d = 0; d < HD; d++) {
            float4 qv = *(const float4*)&qs[d][jg * 4];
            float4 kv = *(const float4*)&ks2[d][kg * 4];
            float qq[4] = {qv.x, qv.y, qv.z, qv.w};
            float kk2[4] = {kv.x, kv.y, kv.z, kv.w};
#pragma unroll
            for (int a = 0; a < 4; a++)
#pragma unroll
                for (int c = 0; c < 4; c++) e[a][c] += qq[a] * kk2[c];
        }
#pragma unroll
        for (int a = 0; a < 4; a++) {
            float mj = ms[jg * 4 + a];
            float4 pv;
            pv.x = exp2f(e[a][0] - mj);
            pv.y = exp2f(e[a][1] - mj);
            pv.z = exp2f(e[a][2] - mj);
            pv.w = exp2f(e[a][3] - mj);
            *(float4*)&ps[jg * 4 + a][kg * 4] = pv;
        }
        __syncthreads();

        // out[dg*8 + r][kq] += sum_jj P[jj][kq] * w[jj][dg*8 + r]
#pragma unroll 4
        for (int jj = 0; jj < TJ; jj++) {
            float p = ps[jj][kq];
            float4 w0 = *(const float4*)&wst[jj][dg * 8];
            float4 w1 = *(const float4*)&wst[jj][dg * 8 + 4];
            acc[0] += p * w0.x; acc[1] += p * w0.y;
            acc[2] += p * w0.z; acc[3] += p * w0.w;
            acc[4] += p * w1.x; acc[5] += p * w1.y;
            acc[6] += p * w1.z; acc[7] += p * w1.w;
        }
    }

    // epilogue: residual add, write NCHW
    int b = bg >> 3, g = bg & 7;
    size_t cbase = ((size_t)b * CH + g * HD + dg * 8) * L + k0 + kq;
#pragma unroll
    for (int r = 0; r < 8; r++) {
        out[cbase + (size_t)r * L] = acc[r] + x[cbase + (size_t)r * L];
    }
}

// ---------------------------------------------------------------------------
extern "C" void kernel_launch(void* const* d_in, const int* in_sizes, int n_in,
                              void* d_out, int out_size)
{
    (void)in_sizes; (void)n_in; (void)out_size;
    const float* x  = (const float*)d_in[0];
    const float* Wq = (const float*)d_in[1];
    const float* bq = (const float*)d_in[2];
    const float* Wk = (const float*)d_in[3];
    const float* bk = (const float*)d_in[4];
    const float* Wv = (const float*)d_in[5];
    const float* bv = (const float*)d_in[6];
    float* out = (float*)d_out;

    dim3 grid(NT, BG);
    qkv_kernel<<<grid, 256>>>(x, Wq, bq, Wk, bk, Wv, bv);
    pass1_kernel<<<grid, 256>>>();
    pass2_kernel<<<grid, 256>>>(x, out);
}

// round 4
// speedup vs baseline: 1.0032x; 1.0014x over previous
#include <cuda_runtime.h>
#include <cuda_bf16.h>

// Problem constants
#define BATCH 4
#define CH    256
#define G     8
#define HD    32
#define L     3136      // 56*56
#define BG    32        // BATCH*G
#define TJ    64
#define TK    64
#define NT    49        // L/64
#define LOG2E 1.4426950408889634f

// Scratch (static device arrays; no allocations allowed)
__device__ float g_q[BG * HD * L];   // (bg, d, l), q pre-scaled by log2(e)
__device__ float g_k[BG * HD * L];   // (bg, d, l)
__device__ float g_v[BG * HD * L];   // (bg, d, l)
__device__ float g_m[BG * L];        // row max (log2 domain)
__device__ float g_rz[BG * L];       // 1 / row sum

// ---------------------------------------------------------------------------
// Kernel 1: grouped 1x1 conv -> q, k, v.  q scaled by log2(e).
// grid (49, 32), block 256
// ---------------------------------------------------------------------------
__global__ void qkv_kernel(const float* __restrict__ x,
                           const float* __restrict__ Wq, const float* __restrict__ bq,
                           const float* __restrict__ Wk, const float* __restrict__ bk,
                           const float* __restrict__ Wv, const float* __restrict__ bv)
{
    int bg = blockIdx.y;
    int l0 = blockIdx.x * 64;
    int b = bg >> 3, g = bg & 7;

    __shared__ float wqs[HD * HD], wks[HD * HD], wvs[HD * HD];
    __shared__ float bqs[HD], bks[HD], bvs[HD];
    __shared__ float xs[HD][64];

    int tid = threadIdx.x;
    for (int i = tid; i < HD * HD; i += 256) {
        wqs[i] = Wq[g * HD * HD + i] * LOG2E;
        wks[i] = Wk[g * HD * HD + i];
        wvs[i] = Wv[g * HD * HD + i];
    }
    if (tid < HD) {
        bqs[tid] = bq[g * HD + tid] * LOG2E;
        bks[tid] = bk[g * HD + tid];
        bvs[tid] = bv[g * HD + tid];
    }
    const float* xp = x + ((size_t)b * CH + g * HD) * L + l0;
    for (int i = tid; i < HD * 64; i += 256) {
        int d = i >> 6, l = i & 63;
        xs[d][l] = xp[(size_t)d * L + l];
    }
    __syncthreads();

    int l  = tid & 63;
    int o0 = (tid >> 6) * 8;
    float qa[8], ka[8], va[8];
#pragma unroll
    for (int r = 0; r < 8; r++) { qa[r] = bqs[o0 + r]; ka[r] = bks[o0 + r]; va[r] = bvs[o0 + r]; }
#pragma unroll
    for (int i = 0; i < HD; i++) {
        float xv = xs[i][l];
#pragma unroll
        for (int r = 0; r < 8; r++) {
            qa[r] += wqs[(o0 + r) * HD + i] * xv;
            ka[r] += wks[(o0 + r) * HD + i] * xv;
            va[r] += wvs[(o0 + r) * HD + i] * xv;
        }
    }
    size_t base = (size_t)bg * HD * L + l0 + l;
#pragma unroll
    for (int r = 0; r < 8; r++) {
        g_q[base + (size_t)(o0 + r) * L] = qa[r];
        g_k[base + (size_t)(o0 + r) * L] = ka[r];
        g_v[base + (size_t)(o0 + r) * L] = va[r];
    }
}

// ---------------------------------------------------------------------------
// Kernel 2: per-row online softmax stats over e[j,k] = q_j . k_k (log2 domain)
// grid (49, 32), block 256.  Thread (jg, kg) owns 4 rows x 4 cols per tile.
// ---------------------------------------------------------------------------
__global__ void pass1_kernel()
{
    int bg = blockIdx.y;
    int j0 = blockIdx.x * TJ;

    __shared__ float qs[HD][TJ];
    __shared__ float ks[HD][TK];

    int tid = threadIdx.x;
    const float* qp = g_q + (size_t)bg * HD * L;
    const float* kp = g_k + (size_t)bg * HD * L;

    for (int i = tid; i < HD * TJ; i += 256) {
        int d = i >> 6, jj = i & 63;
        qs[d][jj] = qp[(size_t)d * L + j0 + jj];
    }

    int jg = tid >> 4;   // 0..15 (row group); 16 lanes per row set = half warp
    int kg = tid & 15;   // 0..15 (col group)

    float m[4], s[4];
#pragma unroll
    for (int r = 0; r < 4; r++) { m[r] = -1e30f; s[r] = 0.f; }

    for (int kt = 0; kt < NT; kt++) {
        __syncthreads();
        for (int i = tid; i < HD * TK; i += 256) {
            int d = i >> 6, kk = i & 63;
            ks[d][kk] = kp[(size_t)d * L + kt * TK + kk];
        }
        __syncthreads();

        float e[4][4];
#pragma unroll
        for (int a = 0; a < 4; a++)
#pragma unroll
            for (int c = 0; c < 4; c++) e[a][c] = 0.f;

#pragma unroll
        for (int d = 0; d < HD; d++) {
            float4 qv = *(const float4*)&qs[d][jg * 4];
            float4 kv = *(const float4*)&ks[d][kg * 4];
            float qq[4] = {qv.x, qv.y, qv.z, qv.w};
            float kk2[4] = {kv.x, kv.y, kv.z, kv.w};
#pragma unroll
            for (int a = 0; a < 4; a++)
#pragma unroll
                for (int c = 0; c < 4; c++) e[a][c] += qq[a] * kk2[c];
        }

#pragma unroll
        for (int a = 0; a < 4; a++) {
            float mx = fmaxf(fmaxf(e[a][0], e[a][1]), fmaxf(e[a][2], e[a][3]));
            float mn = fmaxf(m[a], mx);
            float ss = exp2f(e[a][0] - mn) + exp2f(e[a][1] - mn)
                     + exp2f(e[a][2] - mn) + exp2f(e[a][3] - mn);
            s[a] = s[a] * exp2f(m[a] - mn) + ss;
            m[a] = mn;
        }
    }

    // reduce (m, s) across the 16 lanes sharing each row
#pragma unroll
    for (int mask = 8; mask; mask >>= 1) {
#pragma unroll
        for (int a = 0; a < 4; a++) {
            float om = __shfl_xor_sync(0xffffffff, m[a], mask);
            float os = __shfl_xor_sync(0xffffffff, s[a], mask);
            float mn = fmaxf(m[a], om);
            s[a] = s[a] * exp2f(m[a] - mn) + os * exp2f(om - mn);
            m[a] = mn;
        }
    }
    if (kg == 0) {
#pragma unroll
        for (int a = 0; a < 4; a++) {
            int j = j0 + jg * 4 + a;
            g_m[bg * L + j]  = m[a];
            g_rz[bg * L + j] = 1.0f / s[a];
        }
    }
}

// ---------------------------------------------------------------------------
// Kernel 3: out[d,k] = sum_j exp2(e[j,k]-m_j) * v[d,j]/Z_j   (+ x residual)
// grid (49, 32), block 256.  Block owns 64 output columns x all 32 d.
// ---------------------------------------------------------------------------
__global__ void pass2_kernel(const float* __restrict__ x, float* __restrict__ out)
{
    int bg = blockIdx.y;
    int k0 = blockIdx.x * TK;

    __shared__ float ks2[HD][TK];          // K for our columns (the "queries")
    __shared__ float qs[HD][TJ];           // Q tile (the "keys")
    __shared__ float wst[TJ][HD + 4];      // w = v/Z, transposed [jj][d]
    __shared__ float ps[TJ][TK + 4];       // P tile
    __shared__ float ms[TJ];

    int tid = threadIdx.x;
    const float* qp = g_q + (size_t)bg * HD * L;
    const float* kp = g_k + (size_t)bg * HD * L;
    const float* vp = g_v + (size_t)bg * HD * L;

    for (int i = tid; i < HD * TK; i += 256) {
        int d = i >> 6, kk = i & 63;
        ks2[d][kk] = kp[(size_t)d * L + k0 + kk];
    }

    int jg = tid >> 4, kg = tid & 15;   // P-compute mapping
    int kq = tid & 63;                  // out col
    int dg = tid >> 6;                  // 0..3 -> d base = dg*8

    float acc[8];
#pragma unroll
    for (int r = 0; r < 8; r++) acc[r] = 0.f;

    for (int jt = 0; jt < NT; jt++) {
        __syncthreads();
        int j0 = jt * TJ;
        for (int i = tid; i < HD * TJ; i += 256) {
            int d = i >> 6, jj = i & 63;
            qs[d][jj] = qp[(size_t)d * L + j0 + jj];
            float rz = g_rz[bg * L + j0 + jj];
            wst[jj][d] = vp[(size_t)d * L + j0 + jj] * rz;
        }
        if (tid < TJ) ms[tid] = g_m[bg * L + j0 + tid];
        __syncthreads();

        // P = exp2(Q^T Ks - m)
        float e[4][4];
#pragma unroll
        for (int a = 0; a < 4; a++)
#pragma unroll
            for (int c = 0; c < 4; c++) e[a][c] = 0.f;
#pragma unroll
        for (int d = 0; d < HD; d++) {
            float4 qv = *(const float4*)&qs[d][jg * 4];
            float4 kv = *(const float4*)&ks2[d][kg * 4];
            float qq[4] = {qv.x, qv.y, qv.z, qv.w};
            float kk2[4] = {kv.x, kv.y, kv.z, kv.w};
#pragma unroll
            for (int a = 0; a < 4; a++)
#pragma unroll
                for (int c = 0; c < 4; c++) e[a][c] += qq[a] * kk2[c];
        }
#pragma unroll
        for (int a = 0; a < 4; a++) {
            float mj = ms[jg * 4 + a];
            float4 pv;
            pv.x = exp2f(e[a][0] - mj);
            pv.y = exp2f(e[a][1] - mj);
            pv.z = exp2f(e[a][2] - mj);
            pv.w = exp2f(e[a][3] - mj);
            *(float4*)&ps[jg * 4 + a][kg * 4] = pv;
        }
        __syncthreads();

        // out[dg*8 + r][kq] += sum_jj P[jj][kq] * w[jj][dg*8 + r]
#pragma unroll 4
        for (int jj = 0; jj < TJ; jj++) {
            float p = ps[jj][kq];
            float4 w0 = *(const float4*)&wst[jj][dg * 8];
            float4 w1 = *(const float4*)&wst[jj][dg * 8 + 4];
            acc[0] += p * w0.x; acc[1] += p * w0.y;
            acc[2] += p * w0.z; acc[3] += p * w0.w;
            acc[4] += p * w1.x; acc[5] += p * w1.y;
            acc[6] += p * w1.z; acc[7] += p * w1.w;
        }
    }

    // epilogue: residual add, write NCHW
    int b = bg >> 3, g = bg & 7;
    size_t cbase = ((size_t)b * CH + g * HD + dg * 8) * L + k0 + kq;
#pragma unroll
    for (int r = 0; r < 8; r++) {
        out[cbase + (size_t)r * L] = acc[r] + x[cbase + (size_t)r * L];
    }
}

// ---------------------------------------------------------------------------
extern "C" void kernel_launch(void* const* d_in, const int* in_sizes, int n_in,
                              void* d_out, int out_size)
{
    (void)in_sizes; (void)n_in; (void)out_size;
    const float* x  = (const float*)d_in[0];
    const float* Wq = (const float*)d_in[1];
    const float* bq = (const float*)d_in[2];
    const float* Wk = (const float*)d_in[3];
    const float* bk = (const float*)d_in[4];
    const float* Wv = (const float*)d_in[5];
    const float* bv = (const float*)d_in[6];
    float* out = (float*)d_out;

    dim3 grid(NT, BG);
    qkv_kernel<<<grid, 256>>>(x, Wq, bq, Wk, bk, Wv, bv);
    pass1_kernel<<<grid, 256>>>();
    pass2_kernel<<<grid, 256>>>(x, out);
}